// round 1
// baseline (speedup 1.0000x reference)
#include <cuda_runtime.h>
#include <cstdint>

// Problem constants
#define NVOX (512*512*48)      // 12,582,912 voxels
#define NROWS (512*512)        // 262,144 (y,x) rows of 48 along k
#define MC 4096                // clusters

// ---------------- device scratch (no allocation allowed) ----------------
__device__ unsigned long long g_mk[NROWS];   // bitmask per row (k-axis packed)
__device__ unsigned long long g_m2[NROWS];   // temp for separable erosion
__device__ int g_cnt[MC], g_sx[MC], g_sy[MC], g_sz[MC];
__device__ unsigned long long g_keys[MC];    // sort keys
__device__ float g_cx[MC], g_cy[MC];         // centroid xy (original order)
__device__ unsigned g_mat[MC * 128];         // NMS suppression bit-matrix (sorted order)

// ---------------- stage 1: build 48-bit masks + erode along k ----------------
// One warp per (y,x) row: ballot 48 floats into a 48-bit mask, then 9-wide AND.
__global__ void k_build(const float* __restrict__ prob) {
    int warp = (blockIdx.x * blockDim.x + threadIdx.x) >> 5;
    int lane = threadIdx.x & 31;
    if (warp >= NROWS) return;
    const float* p = prob + (size_t)warp * 48;
    float a = p[lane];
    float b = (lane < 16) ? p[32 + lane] : 0.0f;
    unsigned b0 = __ballot_sync(0xFFFFFFFFu, a > 0.5f);
    unsigned b1 = __ballot_sync(0xFFFFFFFFu, (lane < 16) && (b > 0.5f));
    if (lane == 0) {
        unsigned long long m =
            (unsigned long long)b0 | ((unsigned long long)(b1 & 0xFFFFu) << 32);
        unsigned long long e = m;
        #pragma unroll
        for (int s = 1; s <= 4; s++) e &= (m << s) & (m >> s);
        g_mk[warp] = e;   // bits >= 48 are 0 because m has them 0 and m is in the AND
    }
}

// ---------------- stage 2: erode along x (i1, contiguous rows) ----------------
__global__ void k_erode_y() {
    int r = blockIdx.x * blockDim.x + threadIdx.x;
    if (r >= NROWS) return;
    int i1 = r & 511;
    unsigned long long e = 0ull;
    if (i1 >= 4 && i1 < 508) {
        e = g_mk[r - 4];
        #pragma unroll
        for (int d = -3; d <= 4; d++) e &= g_mk[r + d];
    }
    g_m2[r] = e;
}

// ---------------- stage 3: erode along y (i0, stride-512 rows) ----------------
__global__ void k_erode_x() {
    int r = blockIdx.x * blockDim.x + threadIdx.x;
    if (r >= NROWS) return;
    int i0 = r >> 9;
    unsigned long long e = 0ull;
    if (i0 >= 4 && i0 < 508) {
        e = g_m2[r - 4 * 512];
        #pragma unroll
        for (int d = -3; d <= 4; d++) e &= g_m2[r + d * 512];
    }
    g_mk[r] = e;
}

// ---------------- zero global accumulators (graph-replayed: must re-zero) ---
__global__ void k_zero() {
    int i = blockIdx.x * blockDim.x + threadIdx.x;
    if (i < MC) { g_cnt[i] = 0; g_sx[i] = 0; g_sy[i] = 0; g_sz[i] = 0; }
}

// ---------------- stage 4: hash + histogram (the heavy pass) ----------------
// 4 separate shared arrays -> shared bank = seg % 32 (full spread, no 4x alias).
// Integer accumulation is EXACT and identical to float32 segment_sum here
// (all addends are integers, |partial sums| << 2^24).
extern __shared__ int s_tab[];
__global__ void __launch_bounds__(1024, 2) k_hist(const float* __restrict__ emb) {
    int* sc = s_tab;
    int* sx = s_tab + MC;
    int* sy = s_tab + 2 * MC;
    int* sz = s_tab + 3 * MC;
    for (int t = threadIdx.x; t < 4 * MC; t += blockDim.x) s_tab[t] = 0;
    __syncthreads();

    int stride = gridDim.x * blockDim.x;
    for (int idx = blockIdx.x * blockDim.x + threadIdx.x; idx < NVOX - 1; idx += stride) {
        int row = idx / 48;
        int k = idx - row * 48;
        unsigned long long m = g_mk[row];
        if (!((m >> k) & 1ull)) continue;
        float e0 = emb[idx];
        float e1 = emb[idx + NVOX];
        float e2 = emb[idx + 2 * NVOX];
        if (!(e0 > -2.0f || e1 > -2.0f || e2 > -2.0f)) continue;
        float c0 = rintf(e0 * 25.0f);
        float c1 = rintf(e1 * 25.0f);
        float c2 = rintf(e2 * 25.0f);
        unsigned q0 = (unsigned)fminf(fmaxf(c0 + 128.0f, 0.0f), 255.0f);
        unsigned q1 = (unsigned)fminf(fmaxf(c1 + 128.0f, 0.0f), 255.0f);
        unsigned q2 = (unsigned)fminf(fmaxf(c2 + 128.0f, 0.0f), 255.0f);
        unsigned h = q0 * 73856093u ^ q1 * 19349663u ^ q2 * 83492791u;
        int seg = (int)(h & 4095u);
        atomicAdd(&sc[seg], 1);
        atomicAdd(&sx[seg], (int)c0);
        atomicAdd(&sy[seg], (int)c1);
        atomicAdd(&sz[seg], (int)c2);
    }
    __syncthreads();
    for (int t = threadIdx.x; t < MC; t += blockDim.x) {
        int c = sc[t];
        if (c) {
            atomicAdd(&g_cnt[t], c);
            atomicAdd(&g_sx[t], sx[t]);
            atomicAdd(&g_sy[t], sy[t]);
            atomicAdd(&g_sz[t], sz[t]);
        }
    }
}

// ---------------- stage 5: centroids + sort keys ----------------
__global__ void k_fin(float* __restrict__ out) {
    int i = blockIdx.x * blockDim.x + threadIdx.x;
    if (i >= MC) return;
    int cnt = g_cnt[i];
    float d = fmaxf((float)cnt, 1.0f);
    float cx = (float)g_sx[i] / d;
    float cy = (float)g_sy[i] / d;
    float cz = (float)g_sz[i] / d;
    out[i * 3 + 0] = cx;
    out[i * 3 + 1] = cy;
    out[i * 3 + 2] = cz;
    g_cx[i] = cx;
    g_cy[i] = cy;
    // key: (score+1) << 13 | (4095 - i)  -> descending sort == stable argsort(-scores)
    long long scorep1 = (cnt >= 10) ? (long long)cnt + 1 : 0ll;
    g_keys[i] = ((unsigned long long)scorep1 << 13) | (unsigned)(4095 - i);
}

// ---------------- stage 6: bitonic sort of 4096 keys (descending) ----------
__global__ void k_sort() {
    __shared__ unsigned long long sk[MC];
    int tid = threadIdx.x;
    for (int t = tid; t < MC; t += 1024) sk[t] = ~g_keys[t];  // ascending on complement
    __syncthreads();
    for (int k = 2; k <= MC; k <<= 1) {
        for (int j = k >> 1; j > 0; j >>= 1) {
            for (int t = tid; t < MC / 2; t += 1024) {
                int i = ((t & ~(j - 1)) << 1) | (t & (j - 1));
                int p = i | j;
                bool up = ((i & k) == 0);
                unsigned long long a = sk[i], b = sk[p];
                if ((a > b) == up) { sk[i] = b; sk[p] = a; }
            }
            __syncthreads();
        }
    }
    for (int t = tid; t < MC; t += 1024) g_keys[t] = ~sk[t];
}

// ---------------- stage 7: pairwise suppression bit-matrix (sorted order) ---
__global__ void k_mat() {
    int gid = blockIdx.x * blockDim.x + threadIdx.x;   // 4096*4096 threads
    int i = gid >> 12;
    int j = gid & 4095;
    unsigned long long ki = g_keys[i], kj = g_keys[j];
    int oi = 4095 - (int)(ki & 0x1FFFu);
    int oj = 4095 - (int)(kj & 0x1FFFu);
    float cxi = g_cx[oi], cyi = g_cy[oi];
    float cxj = g_cx[oj], cyj = g_cy[oj];
    float bi0 = cxi - 22.5f, bi1 = cyi - 22.5f, bi2 = cxi + 22.5f, bi3 = cyi + 22.5f;
    float bj0 = cxj - 22.5f, bj1 = cyj - 22.5f, bj2 = cxj + 22.5f, bj3 = cyj + 22.5f;
    float x1 = fmaxf(bi0, bj0), y1 = fmaxf(bi1, bj1);
    float x2 = fminf(bi2, bj2), y2 = fminf(bi3, bj3);
    float inter = fmaxf(x2 - x1, 0.0f) * fmaxf(y2 - y1, 0.0f);
    float a1 = (bi2 - bi0) * (bi3 - bi1);
    float a2 = (bj2 - bj0) * (bj3 - bj1);
    float iou = inter / fmaxf(a1 + a2 - inter, 1e-9f);
    bool sup = (iou > 0.5f) && (j > i);
    unsigned bits = __ballot_sync(0xFFFFFFFFu, sup);
    if ((threadIdx.x & 31) == 0) g_mat[i * 128 + (j >> 5)] = bits;
}

// ---------------- stage 8: single-warp greedy NMS scan ----------------
// Removed set lives in shared (128 words); only KEPT rows touch the matrix,
// suppressed boxes cost ~nothing.
__global__ void k_scan(float* __restrict__ keep_out) {
    __shared__ unsigned sh_rem[128], sh_cand[128], sh_kept[128];
    int lane = threadIdx.x;
    #pragma unroll
    for (int s = 0; s < 4; s++) { sh_rem[s * 32 + lane] = 0u; sh_kept[s * 32 + lane] = 0u; }
    for (int w = 0; w < 128; w++) {
        unsigned long long kk = g_keys[w * 32 + lane];
        unsigned bb = __ballot_sync(0xFFFFFFFFu, (kk >> 13) >= 11ull);  // score >= 10
        if (lane == 0) sh_cand[w] = bb;
    }
    __syncwarp();
    for (int w = 0; w < 128; w++) {
        unsigned cand = sh_cand[w] & ~sh_rem[w];
        while (cand) {
            int b = __ffs(cand) - 1;
            int i = w * 32 + b;
            if (lane == 0) sh_kept[w] |= (1u << b);
            const unsigned* row = g_mat + i * 128;
            sh_rem[lane]      |= row[lane];
            sh_rem[32 + lane] |= row[32 + lane];
            sh_rem[64 + lane] |= row[64 + lane];
            sh_rem[96 + lane] |= row[96 + lane];
            __syncwarp();
            cand &= ~(1u << b);
            cand &= ~sh_rem[w];
        }
    }
    __syncwarp();
    if (keep_out) {
        for (int w = 0; w < 128; w++) {
            unsigned long long kk = g_keys[w * 32 + lane];
            int orig = 4095 - (int)(kk & 0x1FFFu);
            keep_out[orig] = ((sh_kept[w] >> lane) & 1u) ? 1.0f : 0.0f;
        }
    }
}

// ---------------- launch ----------------
extern "C" void kernel_launch(void* const* d_in, const int* in_sizes, int n_in,
                              void* d_out, int out_size) {
    const float* emb  = (const float*)d_in[0];
    const float* prob = (const float*)d_in[1];
    float* out = (float*)d_out;

    k_build<<<(NROWS * 32) / 256, 256>>>(prob);
    k_erode_y<<<NROWS / 256, 256>>>();
    k_erode_x<<<NROWS / 256, 256>>>();
    k_zero<<<(MC + 255) / 256, 256>>>();

    cudaFuncSetAttribute(k_hist, cudaFuncAttributeMaxDynamicSharedMemorySize, 4 * MC * 4);
    k_hist<<<296, 1024, 4 * MC * 4>>>(emb);

    k_fin<<<MC / 256, 256>>>(out);
    k_sort<<<1, 1024>>>();
    k_mat<<<(MC * MC) / 256, 256>>>();

    float* keep_out = (out_size >= MC * 3 + MC) ? (out + MC * 3) : nullptr;
    k_scan<<<1, 32>>>(keep_out);
}